// round 1
// baseline (speedup 1.0000x reference)
#include <cuda_runtime.h>
#include <math.h>

// Problem constants
#define BB 2
#define NSEQ 512
#define CDIM 128
#define HH 8
#define NN (NSEQ * NSEQ)          // 262144
#define RTOT (BB * NN)            // 524288 rows
#define TSZ (BB * HH * NN)        // 4194304 floats per gated tensor

// Scratch (device globals; no allocation allowed)
__device__ float g_Vin[TSZ];
__device__ float g_Vout[TSZ];
__device__ float g_Ein[TSZ];
__device__ float g_Eout[TSZ];
__device__ float g_VaIn[TSZ];
__device__ float g_VaOut[TSZ];

__device__ __forceinline__ float sigmoidf(float x) {
    return 1.0f / (1.0f + __expf(-x));
}

// ---------------------------------------------------------------------------
// Kernel 1: fused LayerNorm + dual projection (e_ln @ [Wv|We]) + bias + gating
// Block: 128 threads, 64 rows of e (fixed b,i; 64 consecutive j).
// Writes 4 gated tensors in [b,h,i,j] layout (coalesced along j).
// ---------------------------------------------------------------------------
__global__ void __launch_bounds__(128) k_gate(
    const float* __restrict__ e, const float* __restrict__ mask,
    const float* __restrict__ lnw, const float* __restrict__ lnb,
    const float* __restrict__ Wv, const float* __restrict__ bv,
    const float* __restrict__ We, const float* __restrict__ be)
{
    extern __shared__ float sm[];
    float* sW    = sm;            // 128 x 64 = 8192
    float* sE    = sm + 8192;     // 64 rows x pitch 132 = 8448
    float* sLnw  = sE + 8448;     // 128
    float* sLnb  = sLnw + 128;    // 128
    float* sBias = sLnb + 128;    // 64
    float* sMask = sBias + 64;    // 64

    const int tid = threadIdx.x;
    const int gr0 = blockIdx.x * 64;          // first global row
    const int b  = gr0 >> 18;
    const int i  = (gr0 >> 9) & (NSEQ - 1);
    const int j0 = gr0 & (NSEQ - 1);

    // Combined weight tile: sW[c*64 + o], o<32 -> Wv, o>=32 -> We
    for (int idx = tid; idx < 8192; idx += 128) {
        int c = idx >> 6, o = idx & 63;
        sW[idx] = (o < 32) ? Wv[c * 32 + o] : We[c * 32 + (o - 32)];
    }
    sLnw[tid] = lnw[tid];
    sLnb[tid] = lnb[tid];
    if (tid < 64) {
        sBias[tid] = (tid < 32) ? bv[tid] : be[tid - 32];
    } else {
        sMask[tid - 64] = mask[gr0 + tid - 64];
    }

    // Load 64x128 e tile (float4, pitch 132 to kill bank conflicts)
    {
        const float4* e4 = (const float4*)(e + (size_t)gr0 * CDIM);
        #pragma unroll
        for (int q = 0; q < 16; q++) {
            int f = q * 128 + tid;
            int lr = f >> 5, c4 = f & 31;
            float4 v = e4[lr * 32 + c4];
            *(float4*)&sE[lr * 132 + c4 * 4] = v;
        }
    }
    __syncthreads();

    // LayerNorm in place: warp w handles rows w*16..w*16+15
    {
        const int w = tid >> 5, lane = tid & 31;
        float4 wv4 = *(float4*)&sLnw[lane * 4];
        float4 bb4 = *(float4*)&sLnb[lane * 4];
        #pragma unroll
        for (int q = 0; q < 16; q++) {
            int lr = w * 16 + q;
            float4 x = *(float4*)&sE[lr * 132 + lane * 4];
            float s  = x.x + x.y + x.z + x.w;
            float s2 = x.x*x.x + x.y*x.y + x.z*x.z + x.w*x.w;
            #pragma unroll
            for (int o = 16; o; o >>= 1) {
                s  += __shfl_xor_sync(0xffffffffu, s,  o);
                s2 += __shfl_xor_sync(0xffffffffu, s2, o);
            }
            float mu  = s * (1.0f / 128.0f);
            float var = s2 * (1.0f / 128.0f) - mu * mu;
            float rstd = rsqrtf(var + 1e-5f);
            x.x = (x.x - mu) * rstd * wv4.x + bb4.x;
            x.y = (x.y - mu) * rstd * wv4.y + bb4.y;
            x.z = (x.z - mu) * rstd * wv4.z + bb4.z;
            x.w = (x.w - mu) * rstd * wv4.w + bb4.w;
            *(float4*)&sE[lr * 132 + lane * 4] = x;
        }
    }
    __syncthreads();

    // GEMM 64x128 @ 128x64 ; thread tile 8 rows x 4 cols (128 thr = 8x16)
    const int ty = tid >> 4, tx = tid & 15;
    float acc[8][4];
    #pragma unroll
    for (int r = 0; r < 8; r++)
        #pragma unroll
        for (int j = 0; j < 4; j++) acc[r][j] = 0.0f;

    const float* eB = sE + (ty * 8) * 132;
    #pragma unroll 2
    for (int c = 0; c < 128; ++c) {
        float4 b4 = *(const float4*)&sW[(c << 6) + (tx << 2)];
        #pragma unroll
        for (int r = 0; r < 8; ++r) {
            float a = eB[r * 132 + c];
            acc[r][0] += a * b4.x;
            acc[r][1] += a * b4.y;
            acc[r][2] += a * b4.z;
            acc[r][3] += a * b4.w;
        }
    }
    __syncthreads();

    // Stage pre-gate outputs (+bias) to smem, pitch 65 (conflict-free column reads)
    #pragma unroll
    for (int r = 0; r < 8; r++) {
        #pragma unroll
        for (int j = 0; j < 4; j++) {
            int col = (tx << 2) + j;
            sE[(ty * 8 + r) * 65 + col] = acc[r][j] + sBias[col];
        }
    }
    __syncthreads();

    // Gate + write. grp: 0=Vin(g@0,l@8) 1=Vout(16/24) 2=Ein(32/40) 3=Eout(48/56)
    {
        const int grp = tid >> 5;
        const int lr2 = tid & 31;
        const int gbase = (grp & 1) * 16 + (grp >> 1) * 32;
        float* dst = (grp == 0) ? g_Vin : (grp == 1) ? g_Vout
                   : (grp == 2) ? g_Ein : g_Eout;
        #pragma unroll
        for (int part = 0; part < 2; part++) {
            int lr = lr2 + part * 32;
            float m = sMask[lr];
            const float* so = sE + lr * 65;
            int jcol = j0 + lr;
            #pragma unroll
            for (int h = 0; h < 8; h++) {
                float gv = so[gbase + h] + m;
                float lv = so[gbase + 8 + h];
                dst[(((b * 8 + h) * NSEQ) + i) * NSEQ + jcol] = sigmoidf(gv) * lv;
            }
        }
    }
}

// ---------------------------------------------------------------------------
// Kernel 2: batched triangular GEMMs (16 batches of 512x512x512 per direction)
// TRANS=false : Va_in [i][j]  = sum_k Ein[bh][i][k] * Vin[bh][j][k]   (NT)
// TRANS=true  : Va_out[i][j]  = sum_k Eout[bh][k][i] * Vout[bh][k][j] (TN)
// 64x64 tile, BK=16, 256 threads, 4x4 per thread, k-major smem tiles.
// ---------------------------------------------------------------------------
template <bool TRANS>
__global__ void __launch_bounds__(256) k_tri()
{
    __shared__ float sA[16][68];
    __shared__ float sB[16][68];

    const float* A  = TRANS ? g_Eout : g_Ein;
    const float* Bm = TRANS ? g_Vout : g_Vin;
    float*       Cm = TRANS ? g_VaOut : g_VaIn;
    const int off = blockIdx.z * NN;
    A += off; Bm += off; Cm += off;

    const int m0 = blockIdx.y * 64, n0 = blockIdx.x * 64;
    const int tid = threadIdx.x;
    const int ty = tid >> 4, tx = tid & 15;

    float acc[4][4];
    #pragma unroll
    for (int r = 0; r < 4; r++)
        #pragma unroll
        for (int j = 0; j < 4; j++) acc[r][j] = 0.0f;

    for (int kk = 0; kk < NSEQ; kk += 16) {
        if (!TRANS) {
            // rows are m/n; transpose into k-major smem
            int rrow = tid >> 2, c4 = tid & 3;
            float4 va = *(const float4*)&A [(m0 + rrow) * NSEQ + kk + c4 * 4];
            float4 vb = *(const float4*)&Bm[(n0 + rrow) * NSEQ + kk + c4 * 4];
            sA[c4*4+0][rrow] = va.x; sA[c4*4+1][rrow] = va.y;
            sA[c4*4+2][rrow] = va.z; sA[c4*4+3][rrow] = va.w;
            sB[c4*4+0][rrow] = vb.x; sB[c4*4+1][rrow] = vb.y;
            sB[c4*4+2][rrow] = vb.z; sB[c4*4+3][rrow] = vb.w;
        } else {
            // rows are k; direct coalesced copy
            int kc = tid >> 4, c4 = tid & 15;
            *(float4*)&sA[kc][c4 * 4] = *(const float4*)&A [(kk + kc) * NSEQ + m0 + c4 * 4];
            *(float4*)&sB[kc][c4 * 4] = *(const float4*)&Bm[(kk + kc) * NSEQ + n0 + c4 * 4];
        }
        __syncthreads();

        #pragma unroll
        for (int k = 0; k < 16; ++k) {
            float4 a4 = *(const float4*)&sA[k][ty << 2];
            float4 b4 = *(const float4*)&sB[k][tx << 2];
            float av[4] = {a4.x, a4.y, a4.z, a4.w};
            float bv[4] = {b4.x, b4.y, b4.z, b4.w};
            #pragma unroll
            for (int r = 0; r < 4; r++)
                #pragma unroll
                for (int j = 0; j < 4; j++)
                    acc[r][j] += av[r] * bv[j];
        }
        __syncthreads();
    }

    #pragma unroll
    for (int r = 0; r < 4; r++) {
        float4 o = make_float4(acc[r][0], acc[r][1], acc[r][2], acc[r][3]);
        *(float4*)&Cm[(m0 + ty * 4 + r) * NSEQ + n0 + (tx << 2)] = o;
    }
}

// ---------------------------------------------------------------------------
// Kernel 3: gather Va (16 heads) + output projection [64x16]@[16x256]
//           + final siglin -> out [row][128]
// Block: 256 threads, 64 rows. Thread tile: 8 rows x (4 g-cols + 4 l-cols).
// ---------------------------------------------------------------------------
__global__ void __launch_bounds__(256) k_out(
    const float* __restrict__ Wo, const float* __restrict__ bo,
    float* __restrict__ out)
{
    __shared__ float sVa[64][17];
    __shared__ float sWo[16 * 256];
    __shared__ float sBo[256];

    const int tid = threadIdx.x;
    const int gr0 = blockIdx.x * 64;
    const int b  = gr0 >> 18;
    const int i  = (gr0 >> 9) & (NSEQ - 1);
    const int j0 = gr0 & (NSEQ - 1);

    #pragma unroll
    for (int q = 0; q < 16; q++) sWo[q * 256 + tid] = Wo[q * 256 + tid];
    sBo[tid] = bo[tid];

    #pragma unroll
    for (int rep = 0; rep < 4; rep++) {
        int f = rep * 256 + tid;
        int hd = f >> 6;          // 0..15
        int jj = f & 63;
        const float* src = (hd < 8) ? g_VaIn : g_VaOut;
        int h = hd & 7;
        sVa[jj][hd] = src[(((b * 8 + h) * NSEQ) + i) * NSEQ + j0 + jj];
    }
    __syncthreads();

    const int ty = tid >> 5, tx = tid & 31;
    float accg[8][4], accl[8][4];
    #pragma unroll
    for (int r = 0; r < 8; r++)
        #pragma unroll
        for (int j = 0; j < 4; j++) { accg[r][j] = 0.0f; accl[r][j] = 0.0f; }

    #pragma unroll
    for (int k = 0; k < 16; ++k) {
        float4 bg = *(const float4*)&sWo[k * 256 + (tx << 2)];
        float4 bl = *(const float4*)&sWo[k * 256 + 128 + (tx << 2)];
        #pragma unroll
        for (int r = 0; r < 8; ++r) {
            float a = sVa[ty * 8 + r][k];
            accg[r][0] += a * bg.x; accg[r][1] += a * bg.y;
            accg[r][2] += a * bg.z; accg[r][3] += a * bg.w;
            accl[r][0] += a * bl.x; accl[r][1] += a * bl.y;
            accl[r][2] += a * bl.z; accl[r][3] += a * bl.w;
        }
    }

    float4 bog = *(const float4*)&sBo[tx << 2];
    float4 bol = *(const float4*)&sBo[128 + (tx << 2)];
    #pragma unroll
    for (int r = 0; r < 8; ++r) {
        int row = gr0 + ty * 8 + r;
        float g0 = accg[r][0] + bog.x, l0 = accl[r][0] + bol.x;
        float g1 = accg[r][1] + bog.y, l1 = accl[r][1] + bol.y;
        float g2 = accg[r][2] + bog.z, l2 = accl[r][2] + bol.z;
        float g3 = accg[r][3] + bog.w, l3 = accl[r][3] + bol.w;
        float4 o;
        o.x = sigmoidf(g0) * l0;
        o.y = sigmoidf(g1) * l1;
        o.z = sigmoidf(g2) * l2;
        o.w = sigmoidf(g3) * l3;
        *(float4*)&out[(size_t)row * 128 + (tx << 2)] = o;
    }
}

// ---------------------------------------------------------------------------
extern "C" void kernel_launch(void* const* d_in, const int* in_sizes, int n_in,
                              void* d_out, int out_size)
{
    const float* e    = (const float*)d_in[0];
    const float* mask = (const float*)d_in[1];
    const float* lnw  = (const float*)d_in[2];
    const float* lnb  = (const float*)d_in[3];
    const float* Wv   = (const float*)d_in[4];
    const float* bv   = (const float*)d_in[5];
    const float* We   = (const float*)d_in[6];
    const float* be   = (const float*)d_in[7];
    const float* Wo   = (const float*)d_in[8];
    const float* bo   = (const float*)d_in[9];
    float* out = (float*)d_out;

    // K1 needs 68096 B dynamic smem (> 48KB default)
    cudaFuncSetAttribute(k_gate, cudaFuncAttributeMaxDynamicSharedMemorySize, 68096);

    k_gate<<<RTOT / 64, 128, 68096>>>(e, mask, lnw, lnb, Wv, bv, We, be);

    dim3 g2(NSEQ / 64, NSEQ / 64, BB * HH);
    k_tri<false><<<g2, 256>>>();
    k_tri<true><<<g2, 256>>>();

    k_out<<<RTOT / 64, 256>>>(Wo, bo, out);
}

// round 7
// speedup vs baseline: 1.5316x; 1.5316x over previous
#include <cuda_runtime.h>
#include <math.h>
#include <stdint.h>

// Problem constants
#define BB 2
#define NSEQ 512
#define CDIM 128
#define HH 8
#define NN (NSEQ * NSEQ)          // 262144
#define RTOT (BB * NN)            // 524288 rows
#define TSZ (BB * HH * NN)        // 4194304 floats per gated tensor

// Scratch (device globals; no allocation allowed)
__device__ float g_Vin[TSZ];
__device__ float g_Vout[TSZ];
__device__ float g_Ein[TSZ];
__device__ float g_Eout[TSZ];
__device__ float g_VaIn[TSZ];
__device__ float g_VaOut[TSZ];

__device__ __forceinline__ float sigmoidf(float x) {
    return 1.0f / (1.0f + __expf(-x));
}

__device__ __forceinline__ float f2tf(float x) {
    uint32_t r;
    asm("cvt.rna.tf32.f32 %0, %1;" : "=r"(r) : "f"(x));
    return __uint_as_float(r);
}

__device__ __forceinline__ void mma_tf32(float c[4],
    uint32_t a0, uint32_t a1, uint32_t a2, uint32_t a3,
    uint32_t b0, uint32_t b1)
{
    asm volatile(
        "mma.sync.aligned.m16n8k8.row.col.f32.tf32.tf32.f32 "
        "{%0,%1,%2,%3}, {%4,%5,%6,%7}, {%8,%9}, {%0,%1,%2,%3};"
        : "+f"(c[0]), "+f"(c[1]), "+f"(c[2]), "+f"(c[3])
        : "r"(a0), "r"(a1), "r"(a2), "r"(a3), "r"(b0), "r"(b1));
}

// ---------------------------------------------------------------------------
// Kernel 1: fused LayerNorm + dual projection (e_ln @ [Wv|We]) + bias + gating
// Block: 128 threads (4 warps), 64 rows of e. tf32 mma GEMM 64x64x128.
// sE pitch 132 (== 4 mod 32): conflict-free mma A-fragment gathers.
// sW [n][k] pitch 132: conflict-free B-fragment gathers.
// ---------------------------------------------------------------------------
__global__ void __launch_bounds__(128) k_gate(
    const float* __restrict__ e, const float* __restrict__ mask,
    const float* __restrict__ lnw, const float* __restrict__ lnb,
    const float* __restrict__ Wv, const float* __restrict__ bv,
    const float* __restrict__ We, const float* __restrict__ be)
{
    extern __shared__ float sm[];
    float* sW    = sm;             // 64 x 132 = 8448  ([n][k])
    float* sE    = sm + 8448;      // 64 x 132 = 8448  ([m][k]); reused as sPre (64x65)
    float* sLnw  = sE + 8448;      // 128
    float* sLnb  = sLnw + 128;     // 128
    float* sBias = sLnb + 128;     // 64
    float* sMask = sBias + 64;     // 64

    const int tid = threadIdx.x;
    const int gr0 = blockIdx.x * 64;
    const int b  = gr0 >> 18;
    const int i  = (gr0 >> 9) & (NSEQ - 1);
    const int j0 = gr0 & (NSEQ - 1);

    // Weight tile transposed: sW[o][c], o<32 -> Wv col o, o>=32 -> We col o-32
    for (int idx = tid; idx < 8192; idx += 128) {
        int c = idx >> 6, o = idx & 63;
        float v = (o < 32) ? Wv[c * 32 + o] : We[c * 32 + (o - 32)];
        sW[o * 132 + c] = f2tf(v);
    }
    sLnw[tid] = lnw[tid];
    sLnb[tid] = lnb[tid];
    if (tid < 64) {
        sBias[tid] = (tid < 32) ? bv[tid] : be[tid - 32];
    } else {
        sMask[tid - 64] = mask[gr0 + tid - 64];
    }

    // Load 64x128 e tile (float4, pitch 132)
    {
        const float4* e4 = (const float4*)(e + (size_t)gr0 * CDIM);
        #pragma unroll
        for (int q = 0; q < 16; q++) {
            int f = q * 128 + tid;
            int lr = f >> 5, c4 = f & 31;
            float4 v = e4[lr * 32 + c4];
            *(float4*)&sE[lr * 132 + c4 * 4] = v;
        }
    }
    __syncthreads();

    // LayerNorm in place (tf32-rounded output)
    {
        const int w = tid >> 5, lane = tid & 31;
        float4 wv4 = *(float4*)&sLnw[lane * 4];
        float4 bb4 = *(float4*)&sLnb[lane * 4];
        #pragma unroll
        for (int q = 0; q < 16; q++) {
            int lr = w * 16 + q;
            float4 x = *(float4*)&sE[lr * 132 + lane * 4];
            float s  = x.x + x.y + x.z + x.w;
            float s2 = x.x*x.x + x.y*x.y + x.z*x.z + x.w*x.w;
            #pragma unroll
            for (int o = 16; o; o >>= 1) {
                s  += __shfl_xor_sync(0xffffffffu, s,  o);
                s2 += __shfl_xor_sync(0xffffffffu, s2, o);
            }
            float mu  = s * (1.0f / 128.0f);
            float var = s2 * (1.0f / 128.0f) - mu * mu;
            float rstd = rsqrtf(var + 1e-5f);
            x.x = f2tf((x.x - mu) * rstd * wv4.x + bb4.x);
            x.y = f2tf((x.y - mu) * rstd * wv4.y + bb4.y);
            x.z = f2tf((x.z - mu) * rstd * wv4.z + bb4.z);
            x.w = f2tf((x.w - mu) * rstd * wv4.w + bb4.w);
            *(float4*)&sE[lr * 132 + lane * 4] = x;
        }
    }
    __syncthreads();

    // mma GEMM: warp w -> rows [w*16, w*16+16), all 64 n-cols. 8 n-tiles.
    const int wid = tid >> 5, lane = tid & 31;
    const int gid = lane >> 2, tg = lane & 3;

    float acc[8][4];
    #pragma unroll
    for (int nt = 0; nt < 8; nt++)
        #pragma unroll
        for (int q = 0; q < 4; q++) acc[nt][q] = 0.0f;

    #pragma unroll 4
    for (int k0 = 0; k0 < 128; k0 += 8) {
        const float* aBase = sE + (wid * 16 + gid) * 132 + k0 + tg;
        uint32_t a0 = __float_as_uint(aBase[0]);
        uint32_t a1 = __float_as_uint(aBase[8 * 132]);
        uint32_t a2 = __float_as_uint(aBase[4]);
        uint32_t a3 = __float_as_uint(aBase[8 * 132 + 4]);
        #pragma unroll
        for (int nt = 0; nt < 8; nt++) {
            const float* bBase = sW + (nt * 8 + gid) * 132 + k0 + tg;
            uint32_t b0 = __float_as_uint(bBase[0]);
            uint32_t b1 = __float_as_uint(bBase[4]);
            mma_tf32(acc[nt], a0, a1, a2, a3, b0, b1);
        }
    }
    __syncthreads();

    // Stage pre-gate (+bias) into sPre (= sE region), pitch 65
    {
        float* sPre = sE;
        int row = wid * 16 + gid;
        #pragma unroll
        for (int nt = 0; nt < 8; nt++) {
            int col = nt * 8 + 2 * tg;
            sPre[row * 65 + col]           = acc[nt][0] + sBias[col];
            sPre[row * 65 + col + 1]       = acc[nt][1] + sBias[col + 1];
            sPre[(row + 8) * 65 + col]     = acc[nt][2] + sBias[col];
            sPre[(row + 8) * 65 + col + 1] = acc[nt][3] + sBias[col + 1];
        }
    }
    __syncthreads();

    // Gate + write. grp: 0=Vin(g@0,l@8) 1=Vout(16/24) 2=Ein(32/40) 3=Eout(48/56)
    {
        const int grp = tid >> 5;
        const int lr2 = tid & 31;
        const int gbase = (grp & 1) * 16 + (grp >> 1) * 32;
        float* dst = (grp == 0) ? g_Vin : (grp == 1) ? g_Vout
                   : (grp == 2) ? g_Ein : g_Eout;
        #pragma unroll
        for (int part = 0; part < 2; part++) {
            int lr = lr2 + part * 32;
            float m = sMask[lr];
            const float* so = sE + lr * 65;
            int jcol = j0 + lr;
            #pragma unroll
            for (int h = 0; h < 8; h++) {
                float gv = so[gbase + h] + m;
                float lv = so[gbase + 8 + h];
                dst[(((b * 8 + h) * NSEQ) + i) * NSEQ + jcol] = sigmoidf(gv) * lv;
            }
        }
    }
}

// ---------------------------------------------------------------------------
// Kernel 2: batched triangular GEMMs via tf32 mma. 128x128 tile, BK=32.
// TRANS=false : Va_in [i][j] = sum_k Ein[i][k]  * Vin[j][k]   (both row-major
//               [m/n][k] in smem, pitch 36 == 4 mod 32; direct copies)
// TRANS=true  : Va_out[i][j] = sum_k Eout[k][i] * Vout[k][j]  (k-major [k][m]
//               in smem, pitch 136 == 8 mod 32; direct copies)
// 256 threads = 8 warps (2m x 4n), warp tile 64x32, 16 mma per k8-step.
// ---------------------------------------------------------------------------
template <bool TRANS>
__global__ void __launch_bounds__(256, 2) k_tri()
{
    __shared__ float sA[4608];   // NT: 128x36; TN: 32x136 (=4352)
    __shared__ float sB[4608];

    const float* A  = TRANS ? g_Eout : g_Ein;
    const float* Bm = TRANS ? g_Vout : g_Vin;
    float*       Cm = TRANS ? g_VaOut : g_VaIn;
    const size_t off = (size_t)blockIdx.z * NN;
    A += off; Bm += off; Cm += off;

    const int m0 = blockIdx.y * 128, n0 = blockIdx.x * 128;
    const int tid  = threadIdx.x;
    const int wid  = tid >> 5, lane = tid & 31;
    const int warp_m = wid >> 2, warp_n = wid & 3;
    const int gid = lane >> 2, tg = lane & 3;

    float acc[4][4][4];
    #pragma unroll
    for (int mt = 0; mt < 4; mt++)
        #pragma unroll
        for (int nt = 0; nt < 4; nt++)
            #pragma unroll
            for (int q = 0; q < 4; q++) acc[mt][nt][q] = 0.0f;

    for (int kk = 0; kk < NSEQ; kk += 32) {
        // ---- stage 128x32 tiles of A and B (tf32-rounded) ----
        if (!TRANS) {
            #pragma unroll
            for (int t = 0; t < 4; t++) {
                int idx = tid + t * 256;           // 0..1023
                int row = idx >> 3, c4 = (idx & 7) * 4;
                float4 va = *(const float4*)&A [(size_t)(m0 + row) * NSEQ + kk + c4];
                float4 vb = *(const float4*)&Bm[(size_t)(n0 + row) * NSEQ + kk + c4];
                va.x = f2tf(va.x); va.y = f2tf(va.y); va.z = f2tf(va.z); va.w = f2tf(va.w);
                vb.x = f2tf(vb.x); vb.y = f2tf(vb.y); vb.z = f2tf(vb.z); vb.w = f2tf(vb.w);
                *(float4*)&sA[row * 36 + c4] = va;
                *(float4*)&sB[row * 36 + c4] = vb;
            }
        } else {
            #pragma unroll
            for (int t = 0; t < 4; t++) {
                int idx = tid + t * 256;           // 0..1023
                int k = idx >> 5, c4 = (idx & 31) * 4;
                float4 va = *(const float4*)&A [(size_t)(kk + k) * NSEQ + m0 + c4];
                float4 vb = *(const float4*)&Bm[(size_t)(kk + k) * NSEQ + n0 + c4];
                va.x = f2tf(va.x); va.y = f2tf(va.y); va.z = f2tf(va.z); va.w = f2tf(va.w);
                vb.x = f2tf(vb.x); vb.y = f2tf(vb.y); vb.z = f2tf(vb.z); vb.w = f2tf(vb.w);
                *(float4*)&sA[k * 136 + c4] = va;
                *(float4*)&sB[k * 136 + c4] = vb;
            }
        }
        __syncthreads();

        #pragma unroll
        for (int ks = 0; ks < 32; ks += 8) {
            uint32_t af[4][4];
            uint32_t bf[4][2];
            #pragma unroll
            for (int mt = 0; mt < 4; mt++) {
                int mrow = warp_m * 64 + mt * 16 + gid;
                if (!TRANS) {
                    const float* p = sA + mrow * 36 + ks + tg;
                    af[mt][0] = __float_as_uint(p[0]);
                    af[mt][1] = __float_as_uint(p[8 * 36]);
                    af[mt][2] = __float_as_uint(p[4]);
                    af[mt][3] = __float_as_uint(p[8 * 36 + 4]);
                } else {
                    af[mt][0] = __float_as_uint(sA[(ks + tg) * 136 + mrow]);
                    af[mt][1] = __float_as_uint(sA[(ks + tg) * 136 + mrow + 8]);
                    af[mt][2] = __float_as_uint(sA[(ks + tg + 4) * 136 + mrow]);
                    af[mt][3] = __float_as_uint(sA[(ks + tg + 4) * 136 + mrow + 8]);
                }
            }
            #pragma unroll
            for (int nt = 0; nt < 4; nt++) {
                int nrow = warp_n * 32 + nt * 8 + gid;
                if (!TRANS) {
                    const float* p = sB + nrow * 36 + ks + tg;
                    bf[nt][0] = __float_as_uint(p[0]);
                    bf[nt][1] = __float_as_uint(p[4]);
                } else {
                    bf[nt][0] = __float_as_uint(sB[(ks + tg) * 136 + nrow]);
                    bf[nt][1] = __float_as_uint(sB[(ks + tg + 4) * 136 + nrow]);
                }
            }
            #pragma unroll
            for (int mt = 0; mt < 4; mt++)
                #pragma unroll
                for (int nt = 0; nt < 4; nt++)
                    mma_tf32(acc[mt][nt], af[mt][0], af[mt][1], af[mt][2], af[mt][3],
                             bf[nt][0], bf[nt][1]);
        }
        __syncthreads();
    }

    // Epilogue: c0,c1 -> (gid, 2tg..+1); c2,c3 -> (gid+8, 2tg..+1)
    #pragma unroll
    for (int mt = 0; mt < 4; mt++) {
        int row = m0 + warp_m * 64 + mt * 16 + gid;
        #pragma unroll
        for (int nt = 0; nt < 4; nt++) {
            int col = n0 + warp_n * 32 + nt * 8 + 2 * tg;
            *(float2*)&Cm[(size_t)row * NSEQ + col] =
                make_float2(acc[mt][nt][0], acc[mt][nt][1]);
            *(float2*)&Cm[(size_t)(row + 8) * NSEQ + col] =
                make_float2(acc[mt][nt][2], acc[mt][nt][3]);
        }
    }
}

// ---------------------------------------------------------------------------
// Kernel 3: gather Va (16 heads) + output projection + final siglin (tf32 mma).
// Block: 256 threads (8 warps), 64 rows x 64 final cols (grid.y=2 col-halves).
// sVa [m][k=16] pitch 20; sW [n=128][k=16] pitch 20. n-tile ordering pairs
// g-col (nt) with its l-col (nt+4) inside the same thread -> no smem staging.
// ---------------------------------------------------------------------------
__global__ void __launch_bounds__(256) k_out(
    const float* __restrict__ Wo, const float* __restrict__ bo,
    float* __restrict__ out)
{
    __shared__ float sVa[64 * 20];
    __shared__ float sW[128 * 20];
    __shared__ float sBo[256];

    const int tid = threadIdx.x;
    const int gr0 = blockIdx.x * 64;
    const int cy  = blockIdx.y;            // col-half: final cols [cy*64, +64)
    const int b  = gr0 >> 18;
    const int i  = (gr0 >> 9) & (NSEQ - 1);
    const int j0 = gr0 & (NSEQ - 1);

    // Stage weights: sW[n][k]; n = wn*64+u: u<32 -> g col (cy*64+wn*32+u),
    // u>=32 -> l col (128 + cy*64 + wn*32 + u-32) = col + 96 pattern.
    #pragma unroll
    for (int t = 0; t < 8; t++) {
        int idx = tid + t * 256;           // 0..2047
        int n = idx >> 4, k = idx & 15;
        int wn = n >> 6, u = n & 63;
        int ocol = ((u < 32) ? 0 : 96) + cy * 64 + wn * 32 + u;
        sW[n * 20 + k] = f2tf(Wo[k * 256 + ocol]);
    }
    sBo[tid] = bo[tid];

    // Gather Va: sVa[jj][hd], hd<8 from VaIn, else VaOut (tf32-rounded)
    #pragma unroll
    for (int rep = 0; rep < 4; rep++) {
        int f = rep * 256 + tid;
        int hd = f >> 6;
        int jj = f & 63;
        const float* src = (hd < 8) ? g_VaIn : g_VaOut;
        int h = hd & 7;
        sVa[jj * 20 + hd] = f2tf(src[(((size_t)(b * 8 + h) * NSEQ) + i) * NSEQ + j0 + jj]);
    }
    __syncthreads();

    const int wid = tid >> 5, lane = tid & 31;
    const int warp_m = wid >> 1, warp_n = wid & 1;
    const int gid = lane >> 2, tg = lane & 3;

    float acc[8][4];
    #pragma unroll
    for (int nt = 0; nt < 8; nt++)
        #pragma unroll
        for (int q = 0; q < 4; q++) acc[nt][q] = 0.0f;

    #pragma unroll
    for (int k0 = 0; k0 < 16; k0 += 8) {
        const float* aBase = sVa + (warp_m * 16 + gid) * 20 + k0 + tg;
        uint32_t a0 = __float_as_uint(aBase[0]);
        uint32_t a1 = __float_as_uint(aBase[8 * 20]);
        uint32_t a2 = __float_as_uint(aBase[4]);
        uint32_t a3 = __float_as_uint(aBase[8 * 20 + 4]);
        #pragma unroll
        for (int nt = 0; nt < 8; nt++) {
            const float* bBase = sW + (warp_n * 64 + nt * 8 + gid) * 20 + k0 + tg;
            uint32_t b0 = __float_as_uint(bBase[0]);
            uint32_t b1 = __float_as_uint(bBase[4]);
            mma_tf32(acc[nt], a0, a1, a2, a3, b0, b1);
        }
    }

    // Final siglin: g from acc[nt], l from acc[nt+4], same thread/regs.
    #pragma unroll
    for (int nt = 0; nt < 4; nt++) {
        int col = cy * 64 + warp_n * 32 + nt * 8 + 2 * tg;
        float bg0 = sBo[col],       bg1 = sBo[col + 1];
        float bl0 = sBo[col + 128], bl1 = sBo[col + 129];
        int row0 = gr0 + warp_m * 16 + gid;

        float g0 = acc[nt][0] + bg0, l0 = acc[nt + 4][0] + bl0;
        float g1 = acc[nt][1] + bg1, l1 = acc[nt + 4][1] + bl1;
        *(float2*)&out[(size_t)row0 * 128 + col] =
            make_float2(sigmoidf(g0) * l0, sigmoidf(g1) * l1);

        float g2 = acc[nt][2] + bg0, l2 = acc[nt + 4][2] + bl0;
        float g3 = acc[nt][3] + bg1, l3 = acc[nt + 4][3] + bl1;
        *(float2*)&out[(size_t)(row0 + 8) * 128 + col] =
            make_float2(sigmoidf(g2) * l2, sigmoidf(g3) * l3);
    }
}

// ---------------------------------------------------------------------------
extern "C" void kernel_launch(void* const* d_in, const int* in_sizes, int n_in,
                              void* d_out, int out_size)
{
    const float* e    = (const float*)d_in[0];
    const float* mask = (const float*)d_in[1];
    const float* lnw  = (const float*)d_in[2];
    const float* lnb  = (const float*)d_in[3];
    const float* Wv   = (const float*)d_in[4];
    const float* bv   = (const float*)d_in[5];
    const float* We   = (const float*)d_in[6];
    const float* be   = (const float*)d_in[7];
    const float* Wo   = (const float*)d_in[8];
    const float* bo   = (const float*)d_in[9];
    float* out = (float*)d_out;

    // k_gate dynamic smem: 17280 floats = 69120 bytes
    cudaFuncSetAttribute(k_gate, cudaFuncAttributeMaxDynamicSharedMemorySize, 69120);

    k_gate<<<RTOT / 64, 128, 69120>>>(e, mask, lnw, lnb, Wv, bv, We, be);

    dim3 g2(NSEQ / 128, NSEQ / 128, BB * HH);
    k_tri<false><<<g2, 256>>>();
    k_tri<true><<<g2, 256>>>();

    k_out<<<dim3(RTOT / 64, 2), 256>>>(Wo, bo, out);
}

// round 8
// speedup vs baseline: 1.5668x; 1.0230x over previous
#include <cuda_runtime.h>
#include <math.h>
#include <stdint.h>

// Problem constants
#define BB 2
#define NSEQ 512
#define CDIM 128
#define HH 8
#define NN (NSEQ * NSEQ)          // 262144
#define RTOT (BB * NN)            // 524288 rows
#define TSZ (BB * HH * NN)        // 4194304 floats per gated tensor

// Scratch (device globals; no allocation allowed)
__device__ float g_Vin[TSZ];
__device__ float g_Vout[TSZ];
__device__ float g_Ein[TSZ];
__device__ float g_Eout[TSZ];
__device__ float g_VaIn[TSZ];
__device__ float g_VaOut[TSZ];

__device__ __forceinline__ float sigmoidf(float x) {
    return 1.0f / (1.0f + __expf(-x));
}

__device__ __forceinline__ float f2tf(float x) {
    uint32_t r;
    asm("cvt.rna.tf32.f32 %0, %1;" : "=r"(r) : "f"(x));
    return __uint_as_float(r);
}

__device__ __forceinline__ void mma_tf32(float c[4],
    uint32_t a0, uint32_t a1, uint32_t a2, uint32_t a3,
    uint32_t b0, uint32_t b1)
{
    asm volatile(
        "mma.sync.aligned.m16n8k8.row.col.f32.tf32.tf32.f32 "
        "{%0,%1,%2,%3}, {%4,%5,%6,%7}, {%8,%9}, {%0,%1,%2,%3};"
        : "+f"(c[0]), "+f"(c[1]), "+f"(c[2]), "+f"(c[3])
        : "r"(a0), "r"(a1), "r"(a2), "r"(a3), "r"(b0), "r"(b1));
}

// ---------------------------------------------------------------------------
// Kernel 1: fused LayerNorm + dual projection (e_ln @ [Wv|We]) + bias + gating
// (unchanged from R7 measured version)
// ---------------------------------------------------------------------------
__global__ void __launch_bounds__(128) k_gate(
    const float* __restrict__ e, const float* __restrict__ mask,
    const float* __restrict__ lnw, const float* __restrict__ lnb,
    const float* __restrict__ Wv, const float* __restrict__ bv,
    const float* __restrict__ We, const float* __restrict__ be)
{
    extern __shared__ float sm[];
    float* sW    = sm;             // 64 x 132 = 8448  ([n][k])
    float* sE    = sm + 8448;      // 64 x 132 = 8448  ([m][k]); reused as sPre (64x65)
    float* sLnw  = sE + 8448;      // 128
    float* sLnb  = sLnw + 128;     // 128
    float* sBias = sLnb + 128;     // 64
    float* sMask = sBias + 64;     // 64

    const int tid = threadIdx.x;
    const int gr0 = blockIdx.x * 64;
    const int b  = gr0 >> 18;
    const int i  = (gr0 >> 9) & (NSEQ - 1);
    const int j0 = gr0 & (NSEQ - 1);

    for (int idx = tid; idx < 8192; idx += 128) {
        int c = idx >> 6, o = idx & 63;
        float v = (o < 32) ? Wv[c * 32 + o] : We[c * 32 + (o - 32)];
        sW[o * 132 + c] = f2tf(v);
    }
    sLnw[tid] = lnw[tid];
    sLnb[tid] = lnb[tid];
    if (tid < 64) {
        sBias[tid] = (tid < 32) ? bv[tid] : be[tid - 32];
    } else {
        sMask[tid - 64] = mask[gr0 + tid - 64];
    }

    {
        const float4* e4 = (const float4*)(e + (size_t)gr0 * CDIM);
        #pragma unroll
        for (int q = 0; q < 16; q++) {
            int f = q * 128 + tid;
            int lr = f >> 5, c4 = f & 31;
            float4 v = e4[lr * 32 + c4];
            *(float4*)&sE[lr * 132 + c4 * 4] = v;
        }
    }
    __syncthreads();

    {
        const int w = tid >> 5, lane = tid & 31;
        float4 wv4 = *(float4*)&sLnw[lane * 4];
        float4 bb4 = *(float4*)&sLnb[lane * 4];
        #pragma unroll
        for (int q = 0; q < 16; q++) {
            int lr = w * 16 + q;
            float4 x = *(float4*)&sE[lr * 132 + lane * 4];
            float s  = x.x + x.y + x.z + x.w;
            float s2 = x.x*x.x + x.y*x.y + x.z*x.z + x.w*x.w;
            #pragma unroll
            for (int o = 16; o; o >>= 1) {
                s  += __shfl_xor_sync(0xffffffffu, s,  o);
                s2 += __shfl_xor_sync(0xffffffffu, s2, o);
            }
            float mu  = s * (1.0f / 128.0f);
            float var = s2 * (1.0f / 128.0f) - mu * mu;
            float rstd = rsqrtf(var + 1e-5f);
            x.x = f2tf((x.x - mu) * rstd * wv4.x + bb4.x);
            x.y = f2tf((x.y - mu) * rstd * wv4.y + bb4.y);
            x.z = f2tf((x.z - mu) * rstd * wv4.z + bb4.z);
            x.w = f2tf((x.w - mu) * rstd * wv4.w + bb4.w);
            *(float4*)&sE[lr * 132 + lane * 4] = x;
        }
    }
    __syncthreads();

    const int wid = tid >> 5, lane = tid & 31;
    const int gid = lane >> 2, tg = lane & 3;

    float acc[8][4];
    #pragma unroll
    for (int nt = 0; nt < 8; nt++)
        #pragma unroll
        for (int q = 0; q < 4; q++) acc[nt][q] = 0.0f;

    #pragma unroll 4
    for (int k0 = 0; k0 < 128; k0 += 8) {
        const float* aBase = sE + (wid * 16 + gid) * 132 + k0 + tg;
        uint32_t a0 = __float_as_uint(aBase[0]);
        uint32_t a1 = __float_as_uint(aBase[8 * 132]);
        uint32_t a2 = __float_as_uint(aBase[4]);
        uint32_t a3 = __float_as_uint(aBase[8 * 132 + 4]);
        #pragma unroll
        for (int nt = 0; nt < 8; nt++) {
            const float* bBase = sW + (nt * 8 + gid) * 132 + k0 + tg;
            uint32_t b0 = __float_as_uint(bBase[0]);
            uint32_t b1 = __float_as_uint(bBase[4]);
            mma_tf32(acc[nt], a0, a1, a2, a3, b0, b1);
        }
    }
    __syncthreads();

    {
        float* sPre = sE;
        int row = wid * 16 + gid;
        #pragma unroll
        for (int nt = 0; nt < 8; nt++) {
            int col = nt * 8 + 2 * tg;
            sPre[row * 65 + col]           = acc[nt][0] + sBias[col];
            sPre[row * 65 + col + 1]       = acc[nt][1] + sBias[col + 1];
            sPre[(row + 8) * 65 + col]     = acc[nt][2] + sBias[col];
            sPre[(row + 8) * 65 + col + 1] = acc[nt][3] + sBias[col + 1];
        }
    }
    __syncthreads();

    {
        const int grp = tid >> 5;
        const int lr2 = tid & 31;
        const int gbase = (grp & 1) * 16 + (grp >> 1) * 32;
        float* dst = (grp == 0) ? g_Vin : (grp == 1) ? g_Vout
                   : (grp == 2) ? g_Ein : g_Eout;
        #pragma unroll
        for (int part = 0; part < 2; part++) {
            int lr = lr2 + part * 32;
            float m = sMask[lr];
            const float* so = sE + lr * 65;
            int jcol = j0 + lr;
            #pragma unroll
            for (int h = 0; h < 8; h++) {
                float gv = so[gbase + h] + m;
                float lv = so[gbase + 8 + h];
                dst[(((b * 8 + h) * NSEQ) + i) * NSEQ + jcol] = sigmoidf(gv) * lv;
            }
        }
    }
}

// ---------------------------------------------------------------------------
// Kernel 2: batched triangular GEMMs, NT and TN merged into one launch.
// blockIdx.z in [0,16) -> NT (Va_in), [16,32) -> TN (Va_out).
// Same 128x128xBK32 tf32 mma structure as the measured R7 version.
// ---------------------------------------------------------------------------
__global__ void __launch_bounds__(256, 2) k_tri2()
{
    __shared__ float sA[4608];   // NT: 128x36; TN: 32x136 (=4352)
    __shared__ float sB[4608];

    const bool TRANS = (blockIdx.z >= 16);
    const int zb = blockIdx.z & 15;

    const float* A  = TRANS ? g_Eout : g_Ein;
    const float* Bm = TRANS ? g_Vout : g_Vin;
    float*       Cm = TRANS ? g_VaOut : g_VaIn;
    const size_t off = (size_t)zb * NN;
    A += off; Bm += off; Cm += off;

    const int m0 = blockIdx.y * 128, n0 = blockIdx.x * 128;
    const int tid  = threadIdx.x;
    const int wid  = tid >> 5, lane = tid & 31;
    const int warp_m = wid >> 2, warp_n = wid & 3;
    const int gid = lane >> 2, tg = lane & 3;

    float acc[4][4][4];
    #pragma unroll
    for (int mt = 0; mt < 4; mt++)
        #pragma unroll
        for (int nt = 0; nt < 4; nt++)
            #pragma unroll
            for (int q = 0; q < 4; q++) acc[mt][nt][q] = 0.0f;

    for (int kk = 0; kk < NSEQ; kk += 32) {
        if (!TRANS) {
            #pragma unroll
            for (int t = 0; t < 4; t++) {
                int idx = tid + t * 256;
                int row = idx >> 3, c4 = (idx & 7) * 4;
                float4 va = *(const float4*)&A [(size_t)(m0 + row) * NSEQ + kk + c4];
                float4 vb = *(const float4*)&Bm[(size_t)(n0 + row) * NSEQ + kk + c4];
                va.x = f2tf(va.x); va.y = f2tf(va.y); va.z = f2tf(va.z); va.w = f2tf(va.w);
                vb.x = f2tf(vb.x); vb.y = f2tf(vb.y); vb.z = f2tf(vb.z); vb.w = f2tf(vb.w);
                *(float4*)&sA[row * 36 + c4] = va;
                *(float4*)&sB[row * 36 + c4] = vb;
            }
        } else {
            #pragma unroll
            for (int t = 0; t < 4; t++) {
                int idx = tid + t * 256;
                int k = idx >> 5, c4 = (idx & 31) * 4;
                float4 va = *(const float4*)&A [(size_t)(kk + k) * NSEQ + m0 + c4];
                float4 vb = *(const float4*)&Bm[(size_t)(kk + k) * NSEQ + n0 + c4];
                va.x = f2tf(va.x); va.y = f2tf(va.y); va.z = f2tf(va.z); va.w = f2tf(va.w);
                vb.x = f2tf(vb.x); vb.y = f2tf(vb.y); vb.z = f2tf(vb.z); vb.w = f2tf(vb.w);
                *(float4*)&sA[k * 136 + c4] = va;
                *(float4*)&sB[k * 136 + c4] = vb;
            }
        }
        __syncthreads();

        #pragma unroll
        for (int ks = 0; ks < 32; ks += 8) {
            uint32_t af[4][4];
            uint32_t bf[4][2];
            #pragma unroll
            for (int mt = 0; mt < 4; mt++) {
                int mrow = warp_m * 64 + mt * 16 + gid;
                if (!TRANS) {
                    const float* p = sA + mrow * 36 + ks + tg;
                    af[mt][0] = __float_as_uint(p[0]);
                    af[mt][1] = __float_as_uint(p[8 * 36]);
                    af[mt][2] = __float_as_uint(p[4]);
                    af[mt][3] = __float_as_uint(p[8 * 36 + 4]);
                } else {
                    af[mt][0] = __float_as_uint(sA[(ks + tg) * 136 + mrow]);
                    af[mt][1] = __float_as_uint(sA[(ks + tg) * 136 + mrow + 8]);
                    af[mt][2] = __float_as_uint(sA[(ks + tg + 4) * 136 + mrow]);
                    af[mt][3] = __float_as_uint(sA[(ks + tg + 4) * 136 + mrow + 8]);
                }
            }
            #pragma unroll
            for (int nt = 0; nt < 4; nt++) {
                int nrow = warp_n * 32 + nt * 8 + gid;
                if (!TRANS) {
                    const float* p = sB + nrow * 36 + ks + tg;
                    bf[nt][0] = __float_as_uint(p[0]);
                    bf[nt][1] = __float_as_uint(p[4]);
                } else {
                    bf[nt][0] = __float_as_uint(sB[(ks + tg) * 136 + nrow]);
                    bf[nt][1] = __float_as_uint(sB[(ks + tg + 4) * 136 + nrow]);
                }
            }
            #pragma unroll
            for (int mt = 0; mt < 4; mt++)
                #pragma unroll
                for (int nt = 0; nt < 4; nt++)
                    mma_tf32(acc[mt][nt], af[mt][0], af[mt][1], af[mt][2], af[mt][3],
                             bf[nt][0], bf[nt][1]);
        }
        __syncthreads();
    }

    #pragma unroll
    for (int mt = 0; mt < 4; mt++) {
        int row = m0 + warp_m * 64 + mt * 16 + gid;
        #pragma unroll
        for (int nt = 0; nt < 4; nt++) {
            int col = n0 + warp_n * 32 + nt * 8 + 2 * tg;
            *(float2*)&Cm[(size_t)row * NSEQ + col] =
                make_float2(acc[mt][nt][0], acc[mt][nt][1]);
            *(float2*)&Cm[(size_t)(row + 8) * NSEQ + col] =
                make_float2(acc[mt][nt][2], acc[mt][nt][3]);
        }
    }
}

// ---------------------------------------------------------------------------
// Kernel 3 v3: output projection + siglin.
// 1024 blocks x 512 rows (full j-range of one (b,i)). Weights staged ONCE per
// block. A-fragments (Va, k=16 heads) loaded directly from global (no smem,
// no per-iter syncs on the mma path). Results staged fp32 to smem; separate
// gate pass writes fully-coalesced float4 rows of `out`.
// 16 iters of 32 rows; warps = 2m x 4n; per warp 8 n-tiles x 2 k-steps.
// ---------------------------------------------------------------------------
__global__ void __launch_bounds__(256) k_out(
    const float* __restrict__ Wo, const float* __restrict__ bo,
    float* __restrict__ out)
{
    extern __shared__ float sm[];
    float* sW   = sm;              // [n=256][k pitch 20] = 5120
    float* sBo  = sm + 5120;       // 256
    float* sOut = sm + 5376;       // [32][pitch 260] = 8320

    const int tid = threadIdx.x;
    const int gr0 = blockIdx.x * 512;          // j0 == 0; spans full j for (b,i)
    const int b  = gr0 >> 18;
    const int i  = (gr0 >> 9) & (NSEQ - 1);

    // Stage Wo transposed: sW[n][k] = Wo[k*256 + n]; coalesced over n.
    #pragma unroll
    for (int t = 0; t < 16; t++) {
        int idx = tid + t * 256;               // 0..4095
        int k = idx >> 8, n = idx & 255;
        sW[n * 20 + k] = f2tf(Wo[k * 256 + n]);
    }
    sBo[tid] = bo[tid];
    __syncthreads();

    const int wid = tid >> 5, lane = tid & 31;
    const int warp_m = wid >> 2, warp_n = wid & 3;   // 2 x 4
    const int gid = lane >> 2, tg = lane & 3;

    const float* baseIn  = g_VaIn  + (size_t)b * 8 * NN + (size_t)i * NSEQ;
    const float* baseOut = g_VaOut + (size_t)b * 8 * NN + (size_t)i * NSEQ;

    for (int it = 0; it < 16; it++) {
        const int rowbase = it * 32;
        const int j = rowbase + warp_m * 16 + gid;   // local row (= global j)

        float acc[8][4];
        #pragma unroll
        for (int nt = 0; nt < 8; nt++)
            #pragma unroll
            for (int q = 0; q < 4; q++) acc[nt][q] = 0.0f;

        #pragma unroll
        for (int k0 = 0; k0 < 16; k0 += 8) {
            const float* src = (k0 == 0) ? baseIn : baseOut;
            uint32_t a0 = __float_as_uint(f2tf(src[(size_t)tg * NN + j]));
            uint32_t a1 = __float_as_uint(f2tf(src[(size_t)tg * NN + j + 8]));
            uint32_t a2 = __float_as_uint(f2tf(src[(size_t)(tg + 4) * NN + j]));
            uint32_t a3 = __float_as_uint(f2tf(src[(size_t)(tg + 4) * NN + j + 8]));
            #pragma unroll
            for (int nt = 0; nt < 8; nt++) {
                int n = warp_n * 64 + nt * 8 + gid;
                uint32_t b0 = __float_as_uint(sW[n * 20 + k0 + tg]);
                uint32_t b1 = __float_as_uint(sW[n * 20 + k0 + tg + 4]);
                mma_tf32(acc[nt], a0, a1, a2, a3, b0, b1);
            }
        }

        // Stage pre-gate results (no bias yet) to sOut [32][260]
        {
            int r = warp_m * 16 + gid;
            #pragma unroll
            for (int nt = 0; nt < 8; nt++) {
                int col = warp_n * 64 + nt * 8 + 2 * tg;
                sOut[r * 260 + col]            = acc[nt][0];
                sOut[r * 260 + col + 1]        = acc[nt][1];
                sOut[(r + 8) * 260 + col]      = acc[nt][2];
                sOut[(r + 8) * 260 + col + 1]  = acc[nt][3];
            }
        }
        __syncthreads();

        // Gate pass: bias + siglin, coalesced float4 stores.
        {
            int row_l = tid >> 3;              // 0..31
            int c0 = (tid & 7) * 4;            // 0..28
            const float* so = sOut + row_l * 260;
            float* od = out + (size_t)(gr0 + rowbase + row_l) * 128;
            #pragma unroll
            for (int q = 0; q < 4; q++) {
                int c = c0 + q * 32;
                float4 g4 = *(float4*)&so[c];
                float4 l4 = *(float4*)&so[c + 128];
                float4 bg = *(float4*)&sBo[c];
                float4 bl = *(float4*)&sBo[c + 128];
                float4 o;
                o.x = sigmoidf(g4.x + bg.x) * (l4.x + bl.x);
                o.y = sigmoidf(g4.y + bg.y) * (l4.y + bl.y);
                o.z = sigmoidf(g4.z + bg.z) * (l4.z + bl.z);
                o.w = sigmoidf(g4.w + bg.w) * (l4.w + bl.w);
                *(float4*)&od[c] = o;
            }
        }
        __syncthreads();   // protect sOut before next iter's STS
    }
}

// ---------------------------------------------------------------------------
extern "C" void kernel_launch(void* const* d_in, const int* in_sizes, int n_in,
                              void* d_out, int out_size)
{
    const float* e    = (const float*)d_in[0];
    const float* mask = (const float*)d_in[1];
    const float* lnw  = (const float*)d_in[2];
    const float* lnb  = (const float*)d_in[3];
    const float* Wv   = (const float*)d_in[4];
    const float* bv   = (const float*)d_in[5];
    const float* We   = (const float*)d_in[6];
    const float* be   = (const float*)d_in[7];
    const float* Wo   = (const float*)d_in[8];
    const float* bo   = (const float*)d_in[9];
    float* out = (float*)d_out;

    cudaFuncSetAttribute(k_gate, cudaFuncAttributeMaxDynamicSharedMemorySize, 69120);
    cudaFuncSetAttribute(k_out,  cudaFuncAttributeMaxDynamicSharedMemorySize, 54784);

    k_gate<<<RTOT / 64, 128, 69120>>>(e, mask, lnw, lnb, Wv, bv, We, be);

    dim3 g2(NSEQ / 128, NSEQ / 128, 2 * BB * HH);
    k_tri2<<<g2, 256>>>();

    k_out<<<RTOT / 512, 256, 54784>>>(Wo, bo, out);
}

// round 10
// speedup vs baseline: 1.7893x; 1.1420x over previous
#include <cuda_runtime.h>
#include <math.h>
#include <stdint.h>

// Problem constants
#define BB 2
#define NSEQ 512
#define CDIM 128
#define HH 8
#define NN (NSEQ * NSEQ)          // 262144
#define RTOT (BB * NN)            // 524288 rows
#define TSZ (BB * HH * NN)        // 4194304 floats per gated tensor

// Scratch (device globals; no allocation allowed)
__device__ float g_Vin[TSZ];
__device__ float g_Vout[TSZ];
__device__ float g_Ein[TSZ];
__device__ float g_Eout[TSZ];
__device__ float g_VaIn[TSZ];
__device__ float g_VaOut[TSZ];

__device__ __forceinline__ float sigmoidf(float x) {
    return 1.0f / (1.0f + __expf(-x));
}

__device__ __forceinline__ float f2tf(float x) {
    uint32_t r;
    asm("cvt.rna.tf32.f32 %0, %1;" : "=r"(r) : "f"(x));
    return __uint_as_float(r);
}

__device__ __forceinline__ void mma_tf32(float c[4],
    uint32_t a0, uint32_t a1, uint32_t a2, uint32_t a3,
    uint32_t b0, uint32_t b1)
{
    asm volatile(
        "mma.sync.aligned.m16n8k8.row.col.f32.tf32.tf32.f32 "
        "{%0,%1,%2,%3}, {%4,%5,%6,%7}, {%8,%9}, {%0,%1,%2,%3};"
        : "+f"(c[0]), "+f"(c[1]), "+f"(c[2]), "+f"(c[3])
        : "r"(a0), "r"(a1), "r"(a2), "r"(a3), "r"(b0), "r"(b1));
}

// ---------------------------------------------------------------------------
// Kernel 1 v2: fused LayerNorm + dual projection + gating.
// 256 threads (8 warps), 128 rows of e per block (grid 4096).
// Weight tile staged once per block, amortized over 2x the rows of R8.
// smem 103168 B -> 2 CTAs/SM (16 warps, 25% occ vs 18.5%).
// sE pitch 132 (==4 mod 32): conflict-free mma A-fragment gathers.
// sW [n][k] pitch 132: conflict-free B-fragment gathers.
// ---------------------------------------------------------------------------
__global__ void __launch_bounds__(256) k_gate(
    const float* __restrict__ e, const float* __restrict__ mask,
    const float* __restrict__ lnw, const float* __restrict__ lnb,
    const float* __restrict__ Wv, const float* __restrict__ bv,
    const float* __restrict__ We, const float* __restrict__ be)
{
    extern __shared__ float sm[];
    float* sW    = sm;              // 64 x 132 = 8448   ([n][k])
    float* sE    = sm + 8448;       // 128 x 132 = 16896 ([m][k]); reused as sPre (128x65)
    float* sLnw  = sE + 16896;      // 128
    float* sLnb  = sLnw + 128;      // 128
    float* sBias = sLnb + 128;      // 64
    float* sMask = sBias + 64;      // 128
    // total 25792 floats = 103168 B

    const int tid = threadIdx.x;
    const int gr0 = blockIdx.x * 128;
    const int b  = gr0 >> 18;
    const int i  = (gr0 >> 9) & (NSEQ - 1);
    const int j0 = gr0 & (NSEQ - 1);

    // Weight tile transposed: sW[o][c], o<32 -> Wv col o, o>=32 -> We col o-32
    for (int idx = tid; idx < 8192; idx += 256) {
        int c = idx >> 6, o = idx & 63;
        float v = (o < 32) ? Wv[c * 32 + o] : We[c * 32 + (o - 32)];
        sW[o * 132 + c] = f2tf(v);
    }
    if (tid < 128) {
        sLnw[tid] = lnw[tid];
        sLnb[tid] = lnb[tid];
        if (tid < 64) sBias[tid] = (tid < 32) ? bv[tid] : be[tid - 32];
    } else {
        sMask[tid - 128] = mask[gr0 + tid - 128];
    }

    // Load 128x128 e tile (float4, pitch 132)
    {
        const float4* e4 = (const float4*)(e + (size_t)gr0 * CDIM);
        #pragma unroll
        for (int q = 0; q < 16; q++) {
            int f = q * 256 + tid;
            int lr = f >> 5, c4 = f & 31;
            float4 v = e4[lr * 32 + c4];
            *(float4*)&sE[lr * 132 + c4 * 4] = v;
        }
    }
    __syncthreads();

    // LayerNorm in place (tf32-rounded). Warp w -> rows [w*16, w*16+16).
    {
        const int w = tid >> 5, lane = tid & 31;
        float4 wv4 = *(float4*)&sLnw[lane * 4];
        float4 bb4 = *(float4*)&sLnb[lane * 4];
        #pragma unroll
        for (int q = 0; q < 16; q++) {
            int lr = w * 16 + q;
            float4 x = *(float4*)&sE[lr * 132 + lane * 4];
            float s  = x.x + x.y + x.z + x.w;
            float s2 = x.x*x.x + x.y*x.y + x.z*x.z + x.w*x.w;
            #pragma unroll
            for (int o = 16; o; o >>= 1) {
                s  += __shfl_xor_sync(0xffffffffu, s,  o);
                s2 += __shfl_xor_sync(0xffffffffu, s2, o);
            }
            float mu  = s * (1.0f / 128.0f);
            float var = s2 * (1.0f / 128.0f) - mu * mu;
            float rstd = rsqrtf(var + 1e-5f);
            x.x = f2tf((x.x - mu) * rstd * wv4.x + bb4.x);
            x.y = f2tf((x.y - mu) * rstd * wv4.y + bb4.y);
            x.z = f2tf((x.z - mu) * rstd * wv4.z + bb4.z);
            x.w = f2tf((x.w - mu) * rstd * wv4.w + bb4.w);
            *(float4*)&sE[lr * 132 + lane * 4] = x;
        }
    }
    __syncthreads();

    // mma GEMM: warp w -> rows [w*16, +16), all 64 n-cols (8 n-tiles).
    const int wid = tid >> 5, lane = tid & 31;
    const int gid = lane >> 2, tg = lane & 3;

    float acc[8][4];
    #pragma unroll
    for (int nt = 0; nt < 8; nt++)
        #pragma unroll
        for (int q = 0; q < 4; q++) acc[nt][q] = 0.0f;

    #pragma unroll 4
    for (int k0 = 0; k0 < 128; k0 += 8) {
        const float* aBase = sE + (wid * 16 + gid) * 132 + k0 + tg;
        uint32_t a0 = __float_as_uint(aBase[0]);
        uint32_t a1 = __float_as_uint(aBase[8 * 132]);
        uint32_t a2 = __float_as_uint(aBase[4]);
        uint32_t a3 = __float_as_uint(aBase[8 * 132 + 4]);
        #pragma unroll
        for (int nt = 0; nt < 8; nt++) {
            const float* bBase = sW + (nt * 8 + gid) * 132 + k0 + tg;
            uint32_t b0 = __float_as_uint(bBase[0]);
            uint32_t b1 = __float_as_uint(bBase[4]);
            mma_tf32(acc[nt], a0, a1, a2, a3, b0, b1);
        }
    }
    __syncthreads();

    // Stage pre-gate (+bias) into sPre (= sE region), pitch 65, 128 rows
    {
        float* sPre = sE;
        int row = wid * 16 + gid;
        #pragma unroll
        for (int nt = 0; nt < 8; nt++) {
            int col = nt * 8 + 2 * tg;
            sPre[row * 65 + col]           = acc[nt][0] + sBias[col];
            sPre[row * 65 + col + 1]       = acc[nt][1] + sBias[col + 1];
            sPre[(row + 8) * 65 + col]     = acc[nt][2] + sBias[col];
            sPre[(row + 8) * 65 + col + 1] = acc[nt][3] + sBias[col + 1];
        }
    }
    __syncthreads();

    // Gate + write. grp = tid>>6: 0=Vin(g@0,l@8) 1=Vout(16/24) 2=Ein(32/40) 3=Eout(48/56)
    {
        const int grp = tid >> 6;
        const int lr2 = tid & 63;
        const int gbase = (grp & 1) * 16 + (grp >> 1) * 32;
        float* dst0 = (grp == 0) ? g_Vin : (grp == 1) ? g_Vout
                    : (grp == 2) ? g_Ein : g_Eout;
        float* dst = dst0 + ((size_t)b * 8 * NSEQ + i) * NSEQ + j0;
        #pragma unroll
        for (int part = 0; part < 2; part++) {
            int lr = lr2 + part * 64;
            float m = sMask[lr];
            const float* so = sE + lr * 65;
            #pragma unroll
            for (int h = 0; h < 8; h++) {
                float gv = so[gbase + h] + m;
                float lv = so[gbase + 8 + h];
                dst[(size_t)h * NN + lr] = sigmoidf(gv) * lv;
            }
        }
    }
}

// ---------------------------------------------------------------------------
// Kernel 2: batched triangular GEMMs, NT and TN merged into one launch.
// blockIdx.z in [0,16) -> NT (Va_in), [16,32) -> TN (Va_out).
// (unchanged from R8 measured version)
// ---------------------------------------------------------------------------
__global__ void __launch_bounds__(256, 2) k_tri2()
{
    __shared__ float sA[4608];   // NT: 128x36; TN: 32x136 (=4352)
    __shared__ float sB[4608];

    const bool TRANS = (blockIdx.z >= 16);
    const int zb = blockIdx.z & 15;

    const float* A  = TRANS ? g_Eout : g_Ein;
    const float* Bm = TRANS ? g_Vout : g_Vin;
    float*       Cm = TRANS ? g_VaOut : g_VaIn;
    const size_t off = (size_t)zb * NN;
    A += off; Bm += off; Cm += off;

    const int m0 = blockIdx.y * 128, n0 = blockIdx.x * 128;
    const int tid  = threadIdx.x;
    const int wid  = tid >> 5, lane = tid & 31;
    const int warp_m = wid >> 2, warp_n = wid & 3;
    const int gid = lane >> 2, tg = lane & 3;

    float acc[4][4][4];
    #pragma unroll
    for (int mt = 0; mt < 4; mt++)
        #pragma unroll
        for (int nt = 0; nt < 4; nt++)
            #pragma unroll
            for (int q = 0; q < 4; q++) acc[mt][nt][q] = 0.0f;

    for (int kk = 0; kk < NSEQ; kk += 32) {
        if (!TRANS) {
            #pragma unroll
            for (int t = 0; t < 4; t++) {
                int idx = tid + t * 256;
                int row = idx >> 3, c4 = (idx & 7) * 4;
                float4 va = *(const float4*)&A [(size_t)(m0 + row) * NSEQ + kk + c4];
                float4 vb = *(const float4*)&Bm[(size_t)(n0 + row) * NSEQ + kk + c4];
                va.x = f2tf(va.x); va.y = f2tf(va.y); va.z = f2tf(va.z); va.w = f2tf(va.w);
                vb.x = f2tf(vb.x); vb.y = f2tf(vb.y); vb.z = f2tf(vb.z); vb.w = f2tf(vb.w);
                *(float4*)&sA[row * 36 + c4] = va;
                *(float4*)&sB[row * 36 + c4] = vb;
            }
        } else {
            #pragma unroll
            for (int t = 0; t < 4; t++) {
                int idx = tid + t * 256;
                int k = idx >> 5, c4 = (idx & 31) * 4;
                float4 va = *(const float4*)&A [(size_t)(kk + k) * NSEQ + m0 + c4];
                float4 vb = *(const float4*)&Bm[(size_t)(kk + k) * NSEQ + n0 + c4];
                va.x = f2tf(va.x); va.y = f2tf(va.y); va.z = f2tf(va.z); va.w = f2tf(va.w);
                vb.x = f2tf(vb.x); vb.y = f2tf(vb.y); vb.z = f2tf(vb.z); vb.w = f2tf(vb.w);
                *(float4*)&sA[k * 136 + c4] = va;
                *(float4*)&sB[k * 136 + c4] = vb;
            }
        }
        __syncthreads();

        #pragma unroll
        for (int ks = 0; ks < 32; ks += 8) {
            uint32_t af[4][4];
            uint32_t bf[4][2];
            #pragma unroll
            for (int mt = 0; mt < 4; mt++) {
                int mrow = warp_m * 64 + mt * 16 + gid;
                if (!TRANS) {
                    const float* p = sA + mrow * 36 + ks + tg;
                    af[mt][0] = __float_as_uint(p[0]);
                    af[mt][1] = __float_as_uint(p[8 * 36]);
                    af[mt][2] = __float_as_uint(p[4]);
                    af[mt][3] = __float_as_uint(p[8 * 36 + 4]);
                } else {
                    af[mt][0] = __float_as_uint(sA[(ks + tg) * 136 + mrow]);
                    af[mt][1] = __float_as_uint(sA[(ks + tg) * 136 + mrow + 8]);
                    af[mt][2] = __float_as_uint(sA[(ks + tg + 4) * 136 + mrow]);
                    af[mt][3] = __float_as_uint(sA[(ks + tg + 4) * 136 + mrow + 8]);
                }
            }
            #pragma unroll
            for (int nt = 0; nt < 4; nt++) {
                int nrow = warp_n * 32 + nt * 8 + gid;
                if (!TRANS) {
                    const float* p = sB + nrow * 36 + ks + tg;
                    bf[nt][0] = __float_as_uint(p[0]);
                    bf[nt][1] = __float_as_uint(p[4]);
                } else {
                    bf[nt][0] = __float_as_uint(sB[(ks + tg) * 136 + nrow]);
                    bf[nt][1] = __float_as_uint(sB[(ks + tg + 4) * 136 + nrow]);
                }
            }
            #pragma unroll
            for (int mt = 0; mt < 4; mt++)
                #pragma unroll
                for (int nt = 0; nt < 4; nt++)
                    mma_tf32(acc[mt][nt], af[mt][0], af[mt][1], af[mt][2], af[mt][3],
                             bf[nt][0], bf[nt][1]);
        }
        __syncthreads();
    }

    #pragma unroll
    for (int mt = 0; mt < 4; mt++) {
        int row = m0 + warp_m * 64 + mt * 16 + gid;
        #pragma unroll
        for (int nt = 0; nt < 4; nt++) {
            int col = n0 + warp_n * 32 + nt * 8 + 2 * tg;
            *(float2*)&Cm[(size_t)row * NSEQ + col] =
                make_float2(acc[mt][nt][0], acc[mt][nt][1]);
            *(float2*)&Cm[(size_t)(row + 8) * NSEQ + col] =
                make_float2(acc[mt][nt][2], acc[mt][nt][3]);
        }
    }
}

// ---------------------------------------------------------------------------
// Kernel 3 v3: output projection + siglin.
// (unchanged from R8 measured version)
// ---------------------------------------------------------------------------
__global__ void __launch_bounds__(256) k_out(
    const float* __restrict__ Wo, const float* __restrict__ bo,
    float* __restrict__ out)
{
    extern __shared__ float sm[];
    float* sW   = sm;              // [n=256][k pitch 20] = 5120
    float* sBo  = sm + 5120;       // 256
    float* sOut = sm + 5376;       // [32][pitch 260] = 8320

    const int tid = threadIdx.x;
    const int gr0 = blockIdx.x * 512;          // spans full j for (b,i)
    const int b  = gr0 >> 18;
    const int i  = (gr0 >> 9) & (NSEQ - 1);

    #pragma unroll
    for (int t = 0; t < 16; t++) {
        int idx = tid + t * 256;               // 0..4095
        int k = idx >> 8, n = idx & 255;
        sW[n * 20 + k] = f2tf(Wo[k * 256 + n]);
    }
    sBo[tid] = bo[tid];
    __syncthreads();

    const int wid = tid >> 5, lane = tid & 31;
    const int warp_m = wid >> 2, warp_n = wid & 3;   // 2 x 4
    const int gid = lane >> 2, tg = lane & 3;

    const float* baseIn  = g_VaIn  + (size_t)b * 8 * NN + (size_t)i * NSEQ;
    const float* baseOut = g_VaOut + (size_t)b * 8 * NN + (size_t)i * NSEQ;

    for (int it = 0; it < 16; it++) {
        const int rowbase = it * 32;
        const int j = rowbase + warp_m * 16 + gid;

        float acc[8][4];
        #pragma unroll
        for (int nt = 0; nt < 8; nt++)
            #pragma unroll
            for (int q = 0; q < 4; q++) acc[nt][q] = 0.0f;

        #pragma unroll
        for (int k0 = 0; k0 < 16; k0 += 8) {
            const float* src = (k0 == 0) ? baseIn : baseOut;
            uint32_t a0 = __float_as_uint(f2tf(src[(size_t)tg * NN + j]));
            uint32_t a1 = __float_as_uint(f2tf(src[(size_t)tg * NN + j + 8]));
            uint32_t a2 = __float_as_uint(f2tf(src[(size_t)(tg + 4) * NN + j]));
            uint32_t a3 = __float_as_uint(f2tf(src[(size_t)(tg + 4) * NN + j + 8]));
            #pragma unroll
            for (int nt = 0; nt < 8; nt++) {
                int n = warp_n * 64 + nt * 8 + gid;
                uint32_t b0 = __float_as_uint(sW[n * 20 + k0 + tg]);
                uint32_t b1 = __float_as_uint(sW[n * 20 + k0 + tg + 4]);
                mma_tf32(acc[nt], a0, a1, a2, a3, b0, b1);
            }
        }

        {
            int r = warp_m * 16 + gid;
            #pragma unroll
            for (int nt = 0; nt < 8; nt++) {
                int col = warp_n * 64 + nt * 8 + 2 * tg;
                sOut[r * 260 + col]            = acc[nt][0];
                sOut[r * 260 + col + 1]        = acc[nt][1];
                sOut[(r + 8) * 260 + col]      = acc[nt][2];
                sOut[(r + 8) * 260 + col + 1]  = acc[nt][3];
            }
        }
        __syncthreads();

        {
            int row_l = tid >> 3;              // 0..31
            int c0 = (tid & 7) * 4;            // 0..28
            const float* so = sOut + row_l * 260;
            float* od = out + (size_t)(gr0 + rowbase + row_l) * 128;
            #pragma unroll
            for (int q = 0; q < 4; q++) {
                int c = c0 + q * 32;
                float4 g4 = *(float4*)&so[c];
                float4 l4 = *(float4*)&so[c + 128];
                float4 bg = *(float4*)&sBo[c];
                float4 bl = *(float4*)&sBo[c + 128];
                float4 o;
                o.x = sigmoidf(g4.x + bg.x) * (l4.x + bl.x);
                o.y = sigmoidf(g4.y + bg.y) * (l4.y + bl.y);
                o.z = sigmoidf(g4.z + bg.z) * (l4.z + bl.z);
                o.w = sigmoidf(g4.w + bg.w) * (l4.w + bl.w);
                *(float4*)&od[c] = o;
            }
        }
        __syncthreads();
    }
}

// ---------------------------------------------------------------------------
extern "C" void kernel_launch(void* const* d_in, const int* in_sizes, int n_in,
                              void* d_out, int out_size)
{
    const float* e    = (const float*)d_in[0];
    const float* mask = (const float*)d_in[1];
    const float* lnw  = (const float*)d_in[2];
    const float* lnb  = (const float*)d_in[3];
    const float* Wv   = (const float*)d_in[4];
    const float* bv   = (const float*)d_in[5];
    const float* We   = (const float*)d_in[6];
    const float* be   = (const float*)d_in[7];
    const float* Wo   = (const float*)d_in[8];
    const float* bo   = (const float*)d_in[9];
    float* out = (float*)d_out;

    cudaFuncSetAttribute(k_gate, cudaFuncAttributeMaxDynamicSharedMemorySize, 103168);
    cudaFuncSetAttribute(k_out,  cudaFuncAttributeMaxDynamicSharedMemorySize, 54784);

    k_gate<<<RTOT / 128, 256, 103168>>>(e, mask, lnw, lnb, Wv, bv, We, be);

    dim3 g2(NSEQ / 128, NSEQ / 128, 2 * BB * HH);
    k_tri2<<<g2, 256>>>();

    k_out<<<RTOT / 512, 256, 54784>>>(Wo, bo, out);
}

// round 17
// speedup vs baseline: 1.9803x; 1.1067x over previous
#include <cuda_runtime.h>
#include <math.h>
#include <stdint.h>

// Problem constants
#define BB 2
#define NSEQ 512
#define CDIM 128
#define HH 8
#define NN (NSEQ * NSEQ)          // 262144
#define RTOT (BB * NN)            // 524288 rows
#define TSZ (BB * HH * NN)        // 4194304 floats per gated tensor

#define GATE_GRID 296             // 2 CTAs x 148 SMs

// Scratch (device globals; no allocation allowed)
__device__ float g_Vin[TSZ];
__device__ float g_Vout[TSZ];
__device__ float g_Ein[TSZ];
__device__ float g_Eout[TSZ];
__device__ float g_VaIn[TSZ];
__device__ float g_VaOut[TSZ];

__device__ __forceinline__ float sigmoidf(float x) {
    return 1.0f / (1.0f + __expf(-x));
}

__device__ __forceinline__ float f2tf(float x) {
    uint32_t r;
    asm("cvt.rna.tf32.f32 %0, %1;" : "=r"(r) : "f"(x));
    return __uint_as_float(r);
}

__device__ __forceinline__ void mma_tf32(float c[4],
    uint32_t a0, uint32_t a1, uint32_t a2, uint32_t a3,
    uint32_t b0, uint32_t b1)
{
    asm volatile(
        "mma.sync.aligned.m16n8k8.row.col.f32.tf32.tf32.f32 "
        "{%0,%1,%2,%3}, {%4,%5,%6,%7}, {%8,%9}, {%0,%1,%2,%3};"
        : "+f"(c[0]), "+f"(c[1]), "+f"(c[2]), "+f"(c[3])
        : "r"(a0), "r"(a1), "r"(a2), "r"(a3), "r"(b0), "r"(b1));
}

__device__ __forceinline__ void cp_async16(uint32_t saddr, const void* gptr) {
    asm volatile("cp.async.cg.shared.global [%0], [%1], 16;"
                 :: "r"(saddr), "l"(gptr));
}

// Prefetch one 64x128 e-tile into smem buffer (pitch 132) via cp.async.
__device__ __forceinline__ void prefetch_tile(float* dst, const float* e,
                                              int tile, int tid)
{
    const float4* src4 = (const float4*)(e + (size_t)tile * 64 * CDIM);
    uint32_t base = (uint32_t)__cvta_generic_to_shared(dst);
    #pragma unroll
    for (int q = 0; q < 8; q++) {
        int f = q * 256 + tid;            // 0..2047
        int lr = f >> 5, c4 = f & 31;
        cp_async16(base + (lr * 132 + c4 * 4) * 4, src4 + f);
    }
}

// ---------------------------------------------------------------------------
// Kernel 1 v3: persistent fused LN + dual projection + gating.
// Grid 296 (2 CTAs/SM), 256 threads. Each CTA loops over 64-row tiles with
// cp.async double buffering: tile t+1 streams in while tile t computes.
// Weights staged once per CTA. smem: sW 8448 + 2 x 8448 bufs + 320 = 102656 B.
// sE/sW pitch 132 (==4 mod 32): conflict-free mma fragment gathers.
// mma: warps 4m x 2n; warp tile 16 rows x 32 cols.
// ---------------------------------------------------------------------------
__global__ void __launch_bounds__(256) k_gate(
    const float* __restrict__ e, const float* __restrict__ mask,
    const float* __restrict__ lnw, const float* __restrict__ lnb,
    const float* __restrict__ Wv, const float* __restrict__ bv,
    const float* __restrict__ We, const float* __restrict__ be)
{
    extern __shared__ float sm[];
    float* sW    = sm;              // 64 x 132 = 8448   ([n][k])
    float* sBuf0 = sm + 8448;       // 64 x 132 = 8448
    float* sBuf1 = sm + 16896;      // 64 x 132 = 8448
    float* sLnw  = sm + 25344;      // 128
    float* sLnb  = sLnw + 128;      // 128
    float* sBias = sLnb + 128;      // 64
    // total 25664 floats = 102656 B

    const int tid = threadIdx.x;

    // Stage weights/LN params once per CTA.
    for (int idx = tid; idx < 8192; idx += 256) {
        int c = idx >> 6, o = idx & 63;
        float v = (o < 32) ? Wv[c * 32 + o] : We[c * 32 + (o - 32)];
        sW[o * 132 + c] = f2tf(v);
    }
    if (tid < 128) {
        sLnw[tid] = lnw[tid];
        sLnb[tid] = lnb[tid];
    } else if (tid < 192) {
        sBias[tid - 128] = (tid < 160) ? bv[tid - 128] : be[tid - 160];
    }

    const int NT = RTOT / 64;        // 8192 tiles
    int tile = blockIdx.x;

    if (tile < NT) prefetch_tile(sBuf0, e, tile, tid);
    asm volatile("cp.async.commit_group;" ::: "memory");
    __syncthreads();                 // sW/params visible

    const int wid = tid >> 5, lane = tid & 31;
    const int warp_m = wid >> 1, warp_n = wid & 1;   // 4m x 2n
    const int gid = lane >> 2, tg = lane & 3;

    int it = 0;
    for (; tile < NT; tile += GATE_GRID, it++) {
        float* cur = (it & 1) ? sBuf1 : sBuf0;
        float* nxt = (it & 1) ? sBuf0 : sBuf1;

        asm volatile("cp.async.wait_group 0;" ::: "memory");
        __syncthreads();             // cur tile data visible to all warps

        // Kick off next tile's loads (overlap with compute below).
        int ntile = tile + GATE_GRID;
        if (ntile < NT) prefetch_tile(nxt, e, ntile, tid);
        asm volatile("cp.async.commit_group;" ::: "memory");

        // LayerNorm in place (tf32-rounded): warp w -> rows [w*8, w*8+8).
        {
            float4 wv4 = *(float4*)&sLnw[lane * 4];
            float4 bb4 = *(float4*)&sLnb[lane * 4];
            #pragma unroll
            for (int q = 0; q < 8; q++) {
                int lr = wid * 8 + q;
                float4 x = *(float4*)&cur[lr * 132 + lane * 4];
                float s  = x.x + x.y + x.z + x.w;
                float s2 = x.x*x.x + x.y*x.y + x.z*x.z + x.w*x.w;
                #pragma unroll
                for (int o = 16; o; o >>= 1) {
                    s  += __shfl_xor_sync(0xffffffffu, s,  o);
                    s2 += __shfl_xor_sync(0xffffffffu, s2, o);
                }
                float mu  = s * (1.0f / 128.0f);
                float var = s2 * (1.0f / 128.0f) - mu * mu;
                float rstd = rsqrtf(var + 1e-5f);
                x.x = f2tf((x.x - mu) * rstd * wv4.x + bb4.x);
                x.y = f2tf((x.y - mu) * rstd * wv4.y + bb4.y);
                x.z = f2tf((x.z - mu) * rstd * wv4.z + bb4.z);
                x.w = f2tf((x.w - mu) * rstd * wv4.w + bb4.w);
                *(float4*)&cur[lr * 132 + lane * 4] = x;
            }
        }
        __syncthreads();

        // mma GEMM 64x64x128: warp tile 16 rows x 32 cols (4 n-tiles).
        float acc[4][4];
        #pragma unroll
        for (int nt = 0; nt < 4; nt++)
            #pragma unroll
            for (int q = 0; q < 4; q++) acc[nt][q] = 0.0f;

        #pragma unroll 4
        for (int k0 = 0; k0 < 128; k0 += 8) {
            const float* aBase = cur + (warp_m * 16 + gid) * 132 + k0 + tg;
            uint32_t a0 = __float_as_uint(aBase[0]);
            uint32_t a1 = __float_as_uint(aBase[8 * 132]);
            uint32_t a2 = __float_as_uint(aBase[4]);
            uint32_t a3 = __float_as_uint(aBase[8 * 132 + 4]);
            #pragma unroll
            for (int nt = 0; nt < 4; nt++) {
                const float* bBase = sW + (warp_n * 32 + nt * 8 + gid) * 132 + k0 + tg;
                uint32_t b0 = __float_as_uint(bBase[0]);
                uint32_t b1 = __float_as_uint(bBase[4]);
                mma_tf32(acc[nt], a0, a1, a2, a3, b0, b1);
            }
        }
        __syncthreads();   // A-fragment reads done before sPre overwrites cur

        // Stage pre-gate (+bias) into sPre (= cur region), pitch 65.
        {
            float* sPre = cur;
            int row = warp_m * 16 + gid;
            #pragma unroll
            for (int nt = 0; nt < 4; nt++) {
                int col = warp_n * 32 + nt * 8 + 2 * tg;
                sPre[row * 65 + col]           = acc[nt][0] + sBias[col];
                sPre[row * 65 + col + 1]       = acc[nt][1] + sBias[col + 1];
                sPre[(row + 8) * 65 + col]     = acc[nt][2] + sBias[col];
                sPre[(row + 8) * 65 + col + 1] = acc[nt][3] + sBias[col + 1];
            }
        }
        __syncthreads();

        // Gate + write. grp = tid>>6: 0=Vin(g@0,l@8) 1=Vout(16/24)
        //                             2=Ein(32/40)  3=Eout(48/56)
        {
            const int gr0 = tile * 64;
            const int b  = gr0 >> 18;
            const int i  = (gr0 >> 9) & (NSEQ - 1);
            const int j0 = gr0 & (NSEQ - 1);
            const int grp = tid >> 6;
            const int lr = tid & 63;
            const int gbase = (grp & 1) * 16 + (grp >> 1) * 32;
            float* dst0 = (grp == 0) ? g_Vin : (grp == 1) ? g_Vout
                        : (grp == 2) ? g_Ein : g_Eout;
            float* dst = dst0 + ((size_t)b * 8 * NSEQ + i) * NSEQ + j0;
            float m = mask[gr0 + lr];
            const float* so = cur + lr * 65;
            #pragma unroll
            for (int h = 0; h < 8; h++) {
                float gv = so[gbase + h] + m;
                float lv = so[gbase + 8 + h];
                dst[(size_t)h * NN + lr] = sigmoidf(gv) * lv;
            }
        }
        __syncthreads();   // gate reads of cur done before its reuse at t+2
    }
}

// ---------------------------------------------------------------------------
// Kernel 2: batched triangular GEMMs, NT and TN merged into one launch.
// (unchanged from R10 measured version)
// ---------------------------------------------------------------------------
__global__ void __launch_bounds__(256, 2) k_tri2()
{
    __shared__ float sA[4608];
    __shared__ float sB[4608];

    const bool TRANS = (blockIdx.z >= 16);
    const int zb = blockIdx.z & 15;

    const float* A  = TRANS ? g_Eout : g_Ein;
    const float* Bm = TRANS ? g_Vout : g_Vin;
    float*       Cm = TRANS ? g_VaOut : g_VaIn;
    const size_t off = (size_t)zb * NN;
    A += off; Bm += off; Cm += off;

    const int m0 = blockIdx.y * 128, n0 = blockIdx.x * 128;
    const int tid  = threadIdx.x;
    const int wid  = tid >> 5, lane = tid & 31;
    const int warp_m = wid >> 2, warp_n = wid & 3;
    const int gid = lane >> 2, tg = lane & 3;

    float acc[4][4][4];
    #pragma unroll
    for (int mt = 0; mt < 4; mt++)
        #pragma unroll
        for (int nt = 0; nt < 4; nt++)
            #pragma unroll
            for (int q = 0; q < 4; q++) acc[mt][nt][q] = 0.0f;

    for (int kk = 0; kk < NSEQ; kk += 32) {
        if (!TRANS) {
            #pragma unroll
            for (int t = 0; t < 4; t++) {
                int idx = tid + t * 256;
                int row = idx >> 3, c4 = (idx & 7) * 4;
                float4 va = *(const float4*)&A [(size_t)(m0 + row) * NSEQ + kk + c4];
                float4 vb = *(const float4*)&Bm[(size_t)(n0 + row) * NSEQ + kk + c4];
                va.x = f2tf(va.x); va.y = f2tf(va.y); va.z = f2tf(va.z); va.w = f2tf(va.w);
                vb.x = f2tf(vb.x); vb.y = f2tf(vb.y); vb.z = f2tf(vb.z); vb.w = f2tf(vb.w);
                *(float4*)&sA[row * 36 + c4] = va;
                *(float4*)&sB[row * 36 + c4] = vb;
            }
        } else {
            #pragma unroll
            for (int t = 0; t < 4; t++) {
                int idx = tid + t * 256;
                int k = idx >> 5, c4 = (idx & 31) * 4;
                float4 va = *(const float4*)&A [(size_t)(kk + k) * NSEQ + m0 + c4];
                float4 vb = *(const float4*)&Bm[(size_t)(kk + k) * NSEQ + n0 + c4];
                va.x = f2tf(va.x); va.y = f2tf(va.y); va.z = f2tf(va.z); va.w = f2tf(va.w);
                vb.x = f2tf(vb.x); vb.y = f2tf(vb.y); vb.z = f2tf(vb.z); vb.w = f2tf(vb.w);
                *(float4*)&sA[k * 136 + c4] = va;
                *(float4*)&sB[k * 136 + c4] = vb;
            }
        }
        __syncthreads();

        #pragma unroll
        for (int ks = 0; ks < 32; ks += 8) {
            uint32_t af[4][4];
            uint32_t bf[4][2];
            #pragma unroll
            for (int mt = 0; mt < 4; mt++) {
                int mrow = warp_m * 64 + mt * 16 + gid;
                if (!TRANS) {
                    const float* p = sA + mrow * 36 + ks + tg;
                    af[mt][0] = __float_as_uint(p[0]);
                    af[mt][1] = __float_as_uint(p[8 * 36]);
                    af[mt][2] = __float_as_uint(p[4]);
                    af[mt][3] = __float_as_uint(p[8 * 36 + 4]);
                } else {
                    af[mt][0] = __float_as_uint(sA[(ks + tg) * 136 + mrow]);
                    af[mt][1] = __float_as_uint(sA[(ks + tg) * 136 + mrow + 8]);
                    af[mt][2] = __float_as_uint(sA[(ks + tg + 4) * 136 + mrow]);
                    af[mt][3] = __float_as_uint(sA[(ks + tg + 4) * 136 + mrow + 8]);
                }
            }
            #pragma unroll
            for (int nt = 0; nt < 4; nt++) {
                int nrow = warp_n * 32 + nt * 8 + gid;
                if (!TRANS) {
                    const float* p = sB + nrow * 36 + ks + tg;
                    bf[nt][0] = __float_as_uint(p[0]);
                    bf[nt][1] = __float_as_uint(p[4]);
                } else {
                    bf[nt][0] = __float_as_uint(sB[(ks + tg) * 136 + nrow]);
                    bf[nt][1] = __float_as_uint(sB[(ks + tg + 4) * 136 + nrow]);
                }
            }
            #pragma unroll
            for (int mt = 0; mt < 4; mt++)
                #pragma unroll
                for (int nt = 0; nt < 4; nt++)
                    mma_tf32(acc[mt][nt], af[mt][0], af[mt][1], af[mt][2], af[mt][3],
                             bf[nt][0], bf[nt][1]);
        }
        __syncthreads();
    }

    #pragma unroll
    for (int mt = 0; mt < 4; mt++) {
        int row = m0 + warp_m * 64 + mt * 16 + gid;
        #pragma unroll
        for (int nt = 0; nt < 4; nt++) {
            int col = n0 + warp_n * 32 + nt * 8 + 2 * tg;
            *(float2*)&Cm[(size_t)row * NSEQ + col] =
                make_float2(acc[mt][nt][0], acc[mt][nt][1]);
            *(float2*)&Cm[(size_t)(row + 8) * NSEQ + col] =
                make_float2(acc[mt][nt][2], acc[mt][nt][3]);
        }
    }
}

// ---------------------------------------------------------------------------
// Kernel 3 v3: output projection + siglin.
// (unchanged from R10 measured version)
// ---------------------------------------------------------------------------
__global__ void __launch_bounds__(256) k_out(
    const float* __restrict__ Wo, const float* __restrict__ bo,
    float* __restrict__ out)
{
    extern __shared__ float sm[];
    float* sW   = sm;              // [n=256][k pitch 20] = 5120
    float* sBo  = sm + 5120;       // 256
    float* sOut = sm + 5376;       // [32][pitch 260] = 8320

    const int tid = threadIdx.x;
    const int gr0 = blockIdx.x * 512;
    const int b  = gr0 >> 18;
    const int i  = (gr0 >> 9) & (NSEQ - 1);

    #pragma unroll
    for (int t = 0; t < 16; t++) {
        int idx = tid + t * 256;
        int k = idx >> 8, n = idx & 255;
        sW[n * 20 + k] = f2tf(Wo[k * 256 + n]);
    }
    sBo[tid] = bo[tid];
    __syncthreads();

    const int wid = tid >> 5, lane = tid & 31;
    const int warp_m = wid >> 2, warp_n = wid & 3;
    const int gid = lane >> 2, tg = lane & 3;

    const float* baseIn  = g_VaIn  + (size_t)b * 8 * NN + (size_t)i * NSEQ;
    const float* baseOut = g_VaOut + (size_t)b * 8 * NN + (size_t)i * NSEQ;

    for (int it = 0; it < 16; it++) {
        const int rowbase = it * 32;
        const int j = rowbase + warp_m * 16 + gid;

        float acc[8][4];
        #pragma unroll
        for (int nt = 0; nt < 8; nt++)
            #pragma unroll
            for (int q = 0; q < 4; q++) acc[nt][q] = 0.0f;

        #pragma unroll
        for (int k0 = 0; k0 < 16; k0 += 8) {
            const float* src = (k0 == 0) ? baseIn : baseOut;
            uint32_t a0 = __float_as_uint(f2tf(src[(size_t)tg * NN + j]));
            uint32_t a1 = __float_as_uint(f2tf(src[(size_t)tg * NN + j + 8]));
            uint32_t a2 = __float_as_uint(f2tf(src[(size_t)(tg + 4) * NN + j]));
            uint32_t a3 = __float_as_uint(f2tf(src[(size_t)(tg + 4) * NN + j + 8]));
            #pragma unroll
            for (int nt = 0; nt < 8; nt++) {
                int n = warp_n * 64 + nt * 8 + gid;
                uint32_t b0 = __float_as_uint(sW[n * 20 + k0 + tg]);
                uint32_t b1 = __float_as_uint(sW[n * 20 + k0 + tg + 4]);
                mma_tf32(acc[nt], a0, a1, a2, a3, b0, b1);
            }
        }

        {
            int r = warp_m * 16 + gid;
            #pragma unroll
            for (int nt = 0; nt < 8; nt++) {
                int col = warp_n * 64 + nt * 8 + 2 * tg;
                sOut[r * 260 + col]            = acc[nt][0];
                sOut[r * 260 + col + 1]        = acc[nt][1];
                sOut[(r + 8) * 260 + col]      = acc[nt][2];
                sOut[(r + 8) * 260 + col + 1]  = acc[nt][3];
            }
        }
        __syncthreads();

        {
            int row_l = tid >> 3;
            int c0 = (tid & 7) * 4;
            const float* so = sOut + row_l * 260;
            float* od = out + (size_t)(gr0 + rowbase + row_l) * 128;
            #pragma unroll
            for (int q = 0; q < 4; q++) {
                int c = c0 + q * 32;
                float4 g4 = *(float4*)&so[c];
                float4 l4 = *(float4*)&so[c + 128];
                float4 bg = *(float4*)&sBo[c];
                float4 bl = *(float4*)&sBo[c + 128];
                float4 o;
                o.x = sigmoidf(g4.x + bg.x) * (l4.x + bl.x);
                o.y = sigmoidf(g4.y + bg.y) * (l4.y + bl.y);
                o.z = sigmoidf(g4.z + bg.z) * (l4.z + bl.z);
                o.w = sigmoidf(g4.w + bg.w) * (l4.w + bl.w);
                *(float4*)&od[c] = o;
            }
        }
        __syncthreads();
    }
}

// ---------------------------------------------------------------------------
extern "C" void kernel_launch(void* const* d_in, const int* in_sizes, int n_in,
                              void* d_out, int out_size)
{
    const float* e    = (const float*)d_in[0];
    const float* mask = (const float*)d_in[1];
    const float* lnw  = (const float*)d_in[2];
    const float* lnb  = (const float*)d_in[3];
    const float* Wv   = (const float*)d_in[4];
    const float* bv   = (const float*)d_in[5];
    const float* We   = (const float*)d_in[6];
    const float* be   = (const float*)d_in[7];
    const float* Wo   = (const float*)d_in[8];
    const float* bo   = (const float*)d_in[9];
    float* out = (float*)d_out;

    cudaFuncSetAttribute(k_gate, cudaFuncAttributeMaxDynamicSharedMemorySize, 102656);
    cudaFuncSetAttribute(k_out,  cudaFuncAttributeMaxDynamicSharedMemorySize, 54784);

    k_gate<<<GATE_GRID, 256, 102656>>>(e, mask, lnw, lnb, Wv, bv, We, be);

    dim3 g2(NSEQ / 128, NSEQ / 128, 2 * BB * HH);
    k_tri2<<<g2, 256>>>();

    k_out<<<RTOT / 512, 256, 54784>>>(Wo, bo, out);
}